// round 4
// baseline (speedup 1.0000x reference)
#include <cuda_runtime.h>
#include <cuda_bf16.h>
#include <math_constants.h>

#define NPARTS 24

// counts scratch: [B][K], B<=64 here but pad generously. __device__ global = allowed scratch.
__device__ float g_counts[8192];

// ---------------------------------------------------------------------------
// Kernel 1: per-batch xyz means + counts.
// Grid = B blocks, 128 threads (4 warps). Each warp owns 1/4 of the N points
// and accumulates into a warp-private, lane-private smem float4 {x,y,z,count}.
// No atomics anywhere.
// ---------------------------------------------------------------------------
__global__ __launch_bounds__(128) void xyz_count_kernel(
    const float* __restrict__ xyz, const int* __restrict__ labels,
    float* __restrict__ out, int N, int C)
{
    const int b = blockIdx.x;
    const int w = threadIdx.x >> 5;
    const int lane = threadIdx.x & 31;

    __shared__ float4 acc[4][NPARTS][32];
    #pragma unroll
    for (int k = 0; k < NPARTS; ++k)
        acc[w][k][lane] = make_float4(0.f, 0.f, 0.f, 0.f);
    __syncwarp();

    const int npw = N >> 2;                       // points per warp
    const float* xb = xyz + (size_t)b * N * 3;
    const int*   lb = labels + (size_t)b * N;
    const int base = w * npw;

    for (int i = lane; i < npw; i += 32) {
        const int n = base + i;
        const int l = lb[n];
        const float x = xb[3*n + 0];
        const float y = xb[3*n + 1];
        const float z = xb[3*n + 2];
        float4 v = acc[w][l][lane];
        v.x += x; v.y += y; v.z += z; v.w += 1.f;
        acc[w][l][lane] = v;
    }
    __syncthreads();

    if (w == 0) {
        const int outd = 3 + 2 * C;
        for (int k = 0; k < NPARTS; ++k) {
            float4 v0 = acc[0][k][lane];
            float4 v1 = acc[1][k][lane];
            float4 v2 = acc[2][k][lane];
            float4 v3 = acc[3][k][lane];
            float sx = v0.x + v1.x + v2.x + v3.x;
            float sy = v0.y + v1.y + v2.y + v3.y;
            float sz = v0.z + v1.z + v2.z + v3.z;
            float sc = v0.w + v1.w + v2.w + v3.w;
            #pragma unroll
            for (int off = 16; off; off >>= 1) {
                sx += __shfl_xor_sync(0xFFFFFFFFu, sx, off);
                sy += __shfl_xor_sync(0xFFFFFFFFu, sy, off);
                sz += __shfl_xor_sync(0xFFFFFFFFu, sz, off);
                sc += __shfl_xor_sync(0xFFFFFFFFu, sc, off);
            }
            if (lane == 0) {
                const float denom = fmaxf(sc, 1.f);
                float* o = out + ((size_t)b * NPARTS + k) * outd;
                o[0] = sx / denom;
                o[1] = sy / denom;
                o[2] = sz / denom;
                g_counts[b * NPARTS + k] = sc;
            }
        }
    }
}

// ---------------------------------------------------------------------------
// Kernel 2: fused segmented sum + segmented max over features.
// One warp per (b, c) channel row; lanes stride over n with float4 loads.
// Lane-private smem accumulators acc[warp][k][lane] = float2{sum, max}.
// surface = max(0, max_f - mean) since mean is constant within a segment.
// Grid = B * C/8 blocks of 8 warps; all warps in a block share batch b, so
// the label row (64 KB) is L1/L2-resident across the 8 channel streams.
// ---------------------------------------------------------------------------
__global__ __launch_bounds__(256) void feat_kernel(
    const float* __restrict__ features, const int* __restrict__ labels,
    float* __restrict__ out, int N, int C)
{
    const int w = threadIdx.x >> 5;
    const int lane = threadIdx.x & 31;
    const int cgroups = C >> 3;
    const int b = blockIdx.x / cgroups;
    const int c = ((blockIdx.x % cgroups) << 3) + w;

    __shared__ float2 acc[8][NPARTS][32];   // 48 KB
    float2* ap = &acc[w][0][lane];          // stride between k's = 32 float2

    #pragma unroll
    for (int k = 0; k < NPARTS; ++k)
        ap[k * 32] = make_float2(0.f, -CUDART_INF_F);
    __syncwarp();

    const float4* __restrict__ frow =
        (const float4*)(features + ((size_t)b * C + c) * N);
    const int4* __restrict__ lrow =
        (const int4*)(labels + (size_t)b * N);

    const int iters = N >> 7;               // 128 n-values per warp iteration
    for (int i = 0; i < iters; ++i) {
        const int idx = (i << 5) + lane;
        const float4 f = frow[idx];
        const int4  l = lrow[idx];
        float2 v;
        v = ap[l.x * 32]; v.x += f.x; v.y = fmaxf(v.y, f.x); ap[l.x * 32] = v;
        v = ap[l.y * 32]; v.x += f.y; v.y = fmaxf(v.y, f.y); ap[l.y * 32] = v;
        v = ap[l.z * 32]; v.x += f.z; v.y = fmaxf(v.y, f.z); ap[l.z * 32] = v;
        v = ap[l.w * 32]; v.x += f.w; v.y = fmaxf(v.y, f.w); ap[l.w * 32] = v;
    }
    __syncwarp();

    const int outd = 3 + 2 * C;
    for (int k = 0; k < NPARTS; ++k) {
        float2 v = ap[k * 32];
        #pragma unroll
        for (int off = 16; off; off >>= 1) {
            v.x += __shfl_xor_sync(0xFFFFFFFFu, v.x, off);
            v.y = fmaxf(v.y, __shfl_xor_sync(0xFFFFFFFFu, v.y, off));
        }
        if (lane == 0) {
            const float cnt = g_counts[b * NPARTS + k];
            const float denom = fmaxf(cnt, 1.f);
            const float mean = v.x / denom;
            // empty segment: v.y = -inf, mean = 0 -> surface = 0 (matches ref)
            const float surf = fmaxf(v.y - mean, 0.f);
            float* o = out + ((size_t)b * NPARTS + k) * outd + 3;
            o[c]     = mean;
            o[C + c] = surf;
        }
    }
}

extern "C" void kernel_launch(void* const* d_in, const int* in_sizes, int n_in,
                              void* d_out, int out_size)
{
    const float* xyz      = (const float*)d_in[0];
    const float* features = (const float*)d_in[1];
    const int*   labels   = (const int*)d_in[2];
    float* out = (float*)d_out;

    const long long BN = in_sizes[2];                 // B*N
    const int C = (int)((long long)in_sizes[1] / BN); // 128
    const int outd = 3 + 2 * C;                        // 259
    const int B = out_size / (NPARTS * outd);          // 64
    const int N = (int)(BN / B);                       // 16384

    xyz_count_kernel<<<B, 128>>>(xyz, labels, out, N, C);
    feat_kernel<<<B * (C / 8), 256>>>(features, labels, out, N, C);
}

// round 5
// speedup vs baseline: 1.1014x; 1.1014x over previous
#include <cuda_runtime.h>
#include <cuda_bf16.h>
#include <math_constants.h>

#define NPARTS 24
#define MAXB   64
#define MAXN   16384
#define SLOTS  8     // xyz partial blocks per batch

// __device__ scratch (allocation-free per harness rules)
__device__ float        g_counts[MAXB * NPARTS];
__device__ unsigned int g_labels8[(MAXB * MAXN) / 4];   // u8-packed labels, 1 MB
__device__ float4       g_part[MAXB * SLOTS * NPARTS];  // partial xyz {x,y,z,count}

// ---------------------------------------------------------------------------
// Kernel 1: per-chunk xyz partial sums + counts, and pack labels to u8.
// Grid = B*SLOTS blocks, 128 threads (4 warps). Lane-private smem float4
// accumulators, no atomics. 4 points per thread-iter via int4 labels and
// 3x float4 xyz loads (fully coalesced).
// ---------------------------------------------------------------------------
__global__ __launch_bounds__(128) void xyz_partial_kernel(
    const float* __restrict__ xyz, const int* __restrict__ labels, int N)
{
    const int b    = blockIdx.x / SLOTS;
    const int s    = blockIdx.x % SLOTS;
    const int w    = threadIdx.x >> 5;
    const int lane = threadIdx.x & 31;

    __shared__ float4 acc[4][NPARTS][32];
    #pragma unroll
    for (int k = 0; k < NPARTS; ++k)
        acc[w][k][lane] = make_float4(0.f, 0.f, 0.f, 0.f);
    __syncwarp();

    const int chunk  = N / SLOTS;             // points per block
    const int groups = chunk >> 2;            // 4-point groups per block
    const int g0     = (b * N + s * chunk) >> 2;  // global 4-point group base

    const int4*   __restrict__ l4 = (const int4*)labels;
    const float4* __restrict__ x4 = (const float4*)xyz;

    for (int g = threadIdx.x; g < groups; g += 128) {
        const int gg = g0 + g;
        const int4 li = l4[gg];
        g_labels8[gg] = (unsigned)li.x | ((unsigned)li.y << 8) |
                        ((unsigned)li.z << 16) | ((unsigned)li.w << 24);
        // 4 points = 12 floats = 3 float4 starting at x4[3*gg]
        const float4 p0 = x4[3 * gg + 0];
        const float4 p1 = x4[3 * gg + 1];
        const float4 p2 = x4[3 * gg + 2];
        float4 v;
        v = acc[w][li.x][lane]; v.x += p0.x; v.y += p0.y; v.z += p0.z; v.w += 1.f; acc[w][li.x][lane] = v;
        v = acc[w][li.y][lane]; v.x += p0.w; v.y += p1.x; v.z += p1.y; v.w += 1.f; acc[w][li.y][lane] = v;
        v = acc[w][li.z][lane]; v.x += p1.z; v.y += p1.w; v.z += p2.x; v.w += 1.f; acc[w][li.z][lane] = v;
        v = acc[w][li.w][lane]; v.x += p2.y; v.y += p2.z; v.z += p2.w; v.w += 1.f; acc[w][li.w][lane] = v;
    }
    __syncthreads();

    if (w == 0) {
        for (int k = 0; k < NPARTS; ++k) {
            const float4 a0 = acc[0][k][lane], a1 = acc[1][k][lane];
            const float4 a2 = acc[2][k][lane], a3 = acc[3][k][lane];
            float4 v = make_float4(a0.x + a1.x + a2.x + a3.x,
                                   a0.y + a1.y + a2.y + a3.y,
                                   a0.z + a1.z + a2.z + a3.z,
                                   a0.w + a1.w + a2.w + a3.w);
            #pragma unroll
            for (int off = 16; off; off >>= 1) {
                v.x += __shfl_xor_sync(0xFFFFFFFFu, v.x, off);
                v.y += __shfl_xor_sync(0xFFFFFFFFu, v.y, off);
                v.z += __shfl_xor_sync(0xFFFFFFFFu, v.z, off);
                v.w += __shfl_xor_sync(0xFFFFFFFFu, v.w, off);
            }
            if (lane == 0)
                g_part[(b * SLOTS + s) * NPARTS + k] = v;
        }
    }
}

// ---------------------------------------------------------------------------
// Kernel 2: merge xyz partials -> mean_xyz in out, counts to g_counts.
// One thread per (b,k).
// ---------------------------------------------------------------------------
__global__ void xyz_merge_kernel(float* __restrict__ out, int C, int B)
{
    const int i = blockIdx.x * blockDim.x + threadIdx.x;
    if (i >= B * NPARTS) return;
    const int b = i / NPARTS, k = i % NPARTS;
    float4 t = make_float4(0.f, 0.f, 0.f, 0.f);
    #pragma unroll
    for (int s = 0; s < SLOTS; ++s) {
        const float4 v = g_part[(b * SLOTS + s) * NPARTS + k];
        t.x += v.x; t.y += v.y; t.z += v.z; t.w += v.w;
    }
    const float denom = fmaxf(t.w, 1.f);
    const int outd = 3 + 2 * C;
    float* o = out + (size_t)i * outd;
    o[0] = t.x / denom;
    o[1] = t.y / denom;
    o[2] = t.z / denom;
    g_counts[i] = t.w;
}

// ---------------------------------------------------------------------------
// Kernel 3: fused segmented sum + max over features.
// Each warp owns TWO channel rows (c0, c0+1); their state is fused into one
// float4 smem cell {sumA, maxA, sumB, maxB} -> half the LDS/STS instruction
// count per value vs float2-per-channel. Labels come pre-packed as u8
// (1 LDG.32 per 128 points per warp). surface = max(0, max_f - mean).
// Grid = B * C/8 blocks of 4 warps (48 KB static smem, 4 blocks/SM).
// ---------------------------------------------------------------------------
__global__ __launch_bounds__(128) void feat_kernel(
    const float* __restrict__ features, float* __restrict__ out, int N, int C)
{
    const int w    = threadIdx.x >> 5;
    const int lane = threadIdx.x & 31;
    const int cgroups = C >> 3;               // 8 channels per block
    const int b  = blockIdx.x / cgroups;
    const int c0 = ((blockIdx.x % cgroups) << 3) + (w << 1);

    __shared__ float4 acc[4][NPARTS][32];     // 48 KB
    float4* ap = &acc[w][0][lane];            // stride between k's = 32 float4

    #pragma unroll
    for (int k = 0; k < NPARTS; ++k)
        ap[k * 32] = make_float4(0.f, -CUDART_INF_F, 0.f, -CUDART_INF_F);
    __syncwarp();

    const float4* __restrict__ fA =
        (const float4*)(features + ((size_t)b * C + c0) * N);
    const float4* __restrict__ fB =
        (const float4*)(features + ((size_t)b * C + c0 + 1) * N);
    const unsigned* __restrict__ lr = g_labels8 + (((size_t)b * N) >> 2);

    const int iters = N >> 7;                 // 128 points per warp-iter
    #pragma unroll 2
    for (int i = 0; i < iters; ++i) {
        const int idx = (i << 5) + lane;
        const float4 a  = fA[idx];
        const float4 bb = fB[idx];
        const unsigned lab = lr[idx];
        const int k0 = lab & 255, k1 = (lab >> 8) & 255,
                  k2 = (lab >> 16) & 255, k3 = lab >> 24;
        float4 v;
        v = ap[k0 * 32]; v.x += a.x; v.y = fmaxf(v.y, a.x); v.z += bb.x; v.w = fmaxf(v.w, bb.x); ap[k0 * 32] = v;
        v = ap[k1 * 32]; v.x += a.y; v.y = fmaxf(v.y, a.y); v.z += bb.y; v.w = fmaxf(v.w, bb.y); ap[k1 * 32] = v;
        v = ap[k2 * 32]; v.x += a.z; v.y = fmaxf(v.y, a.z); v.z += bb.z; v.w = fmaxf(v.w, bb.z); ap[k2 * 32] = v;
        v = ap[k3 * 32]; v.x += a.w; v.y = fmaxf(v.y, a.w); v.z += bb.w; v.w = fmaxf(v.w, bb.w); ap[k3 * 32] = v;
    }
    __syncwarp();

    const int outd = 3 + 2 * C;
    for (int k = 0; k < NPARTS; ++k) {
        float4 v = ap[k * 32];
        #pragma unroll
        for (int off = 16; off; off >>= 1) {
            v.x += __shfl_xor_sync(0xFFFFFFFFu, v.x, off);
            v.y = fmaxf(v.y, __shfl_xor_sync(0xFFFFFFFFu, v.y, off));
            v.z += __shfl_xor_sync(0xFFFFFFFFu, v.z, off);
            v.w = fmaxf(v.w, __shfl_xor_sync(0xFFFFFFFFu, v.w, off));
        }
        if (lane == 0) {
            const float denom = fmaxf(g_counts[b * NPARTS + k], 1.f);
            const float mA = v.x / denom;
            const float mB = v.z / denom;
            float* o = out + ((size_t)b * NPARTS + k) * outd + 3;
            o[c0]         = mA;
            o[c0 + 1]     = mB;
            o[C + c0]     = fmaxf(v.y - mA, 0.f);  // empty seg: -inf - 0 -> 0
            o[C + c0 + 1] = fmaxf(v.w - mB, 0.f);
        }
    }
}

extern "C" void kernel_launch(void* const* d_in, const int* in_sizes, int n_in,
                              void* d_out, int out_size)
{
    const float* xyz      = (const float*)d_in[0];
    const float* features = (const float*)d_in[1];
    const int*   labels   = (const int*)d_in[2];
    float* out = (float*)d_out;

    const long long BN = in_sizes[2];                  // B*N
    const int C = (int)((long long)in_sizes[1] / BN);  // 128
    const int outd = 3 + 2 * C;                        // 259
    const int B = out_size / (NPARTS * outd);          // 64
    const int N = (int)(BN / B);                       // 16384

    xyz_partial_kernel<<<B * SLOTS, 128>>>(xyz, labels, N);
    xyz_merge_kernel<<<(B * NPARTS + 127) / 128, 128>>>(out, C, B);
    feat_kernel<<<B * (C / 8), 128>>>(features, out, N, C);
}

// round 6
// speedup vs baseline: 1.1743x; 1.0662x over previous
#include <cuda_runtime.h>
#include <cuda_bf16.h>
#include <math_constants.h>

#define NPARTS 24
#define MAXB   64
#define MAXN   16384
#define SLOTS  16    // xyz partial blocks per batch

// __device__ scratch (allocation-free per harness rules)
__device__ float        g_counts[MAXB * NPARTS];
__device__ unsigned int g_labels8[(MAXB * MAXN) / 4];   // u8-packed labels, 1 MB
__device__ float4       g_part[MAXB * SLOTS * NPARTS];  // partial xyz {x,y,z,count}

// ---------------------------------------------------------------------------
// Kernel 1: per-chunk xyz partial sums + counts, and pack labels to u8.
// Grid = B*SLOTS blocks, 128 threads (4 warps). Lane-private smem float4
// accumulators, no atomics. 4 points per thread-iter via int4 labels and
// 3x float4 xyz loads (fully coalesced).
// ---------------------------------------------------------------------------
__global__ __launch_bounds__(128) void xyz_partial_kernel(
    const float* __restrict__ xyz, const int* __restrict__ labels, int N)
{
    const int b    = blockIdx.x / SLOTS;
    const int s    = blockIdx.x % SLOTS;
    const int w    = threadIdx.x >> 5;
    const int lane = threadIdx.x & 31;

    __shared__ float4 acc[4][NPARTS][32];
    #pragma unroll
    for (int k = 0; k < NPARTS; ++k)
        acc[w][k][lane] = make_float4(0.f, 0.f, 0.f, 0.f);
    __syncwarp();

    const int chunk  = N / SLOTS;                 // points per block
    const int groups = chunk >> 2;                // 4-point groups per block
    const int g0     = (b * N + s * chunk) >> 2;  // global 4-point group base

    const int4*   __restrict__ l4 = (const int4*)labels;
    const float4* __restrict__ x4 = (const float4*)xyz;

    for (int g = threadIdx.x; g < groups; g += 128) {
        const int gg = g0 + g;
        const int4 li = l4[gg];
        g_labels8[gg] = (unsigned)li.x | ((unsigned)li.y << 8) |
                        ((unsigned)li.z << 16) | ((unsigned)li.w << 24);
        const float4 p0 = x4[3 * gg + 0];
        const float4 p1 = x4[3 * gg + 1];
        const float4 p2 = x4[3 * gg + 2];
        float4 v;
        v = acc[w][li.x][lane]; v.x += p0.x; v.y += p0.y; v.z += p0.z; v.w += 1.f; acc[w][li.x][lane] = v;
        v = acc[w][li.y][lane]; v.x += p0.w; v.y += p1.x; v.z += p1.y; v.w += 1.f; acc[w][li.y][lane] = v;
        v = acc[w][li.z][lane]; v.x += p1.z; v.y += p1.w; v.z += p2.x; v.w += 1.f; acc[w][li.z][lane] = v;
        v = acc[w][li.w][lane]; v.x += p2.y; v.y += p2.z; v.z += p2.w; v.w += 1.f; acc[w][li.w][lane] = v;
    }
    __syncthreads();

    if (w == 0) {
        for (int k = 0; k < NPARTS; ++k) {
            const float4 a0 = acc[0][k][lane], a1 = acc[1][k][lane];
            const float4 a2 = acc[2][k][lane], a3 = acc[3][k][lane];
            float4 v = make_float4(a0.x + a1.x + a2.x + a3.x,
                                   a0.y + a1.y + a2.y + a3.y,
                                   a0.z + a1.z + a2.z + a3.z,
                                   a0.w + a1.w + a2.w + a3.w);
            #pragma unroll
            for (int off = 16; off; off >>= 1) {
                v.x += __shfl_xor_sync(0xFFFFFFFFu, v.x, off);
                v.y += __shfl_xor_sync(0xFFFFFFFFu, v.y, off);
                v.z += __shfl_xor_sync(0xFFFFFFFFu, v.z, off);
                v.w += __shfl_xor_sync(0xFFFFFFFFu, v.w, off);
            }
            if (lane == 0)
                g_part[(b * SLOTS + s) * NPARTS + k] = v;
        }
    }
}

// ---------------------------------------------------------------------------
// Kernel 2: merge xyz partials -> mean_xyz in out, counts to g_counts.
// ---------------------------------------------------------------------------
__global__ void xyz_merge_kernel(float* __restrict__ out, int C, int B)
{
    const int i = blockIdx.x * blockDim.x + threadIdx.x;
    if (i >= B * NPARTS) return;
    float4 t = make_float4(0.f, 0.f, 0.f, 0.f);
    #pragma unroll
    for (int s = 0; s < SLOTS; ++s) {
        const float4 v = g_part[(i / NPARTS * SLOTS + s) * NPARTS + i % NPARTS];
        t.x += v.x; t.y += v.y; t.z += v.z; t.w += v.w;
    }
    const float denom = fmaxf(t.w, 1.f);
    const int outd = 3 + 2 * C;
    float* o = out + (size_t)i * outd;
    o[0] = t.x / denom;
    o[1] = t.y / denom;
    o[2] = t.z / denom;
    g_counts[i] = t.w;
}

// ---------------------------------------------------------------------------
// Kernel 3: fused segmented sum + max over features.
// One warp per channel, float2{sum,max} lane-private accumulators (6 KB/warp
// -> 24 KB per 4-warp block -> 9 blocks = 36 warps/SM for DRAM MLP).
// Software-pipelined: next iteration's 2x LDG.128 + 2x LDG.32 (u8 labels)
// are issued before the current 8-RMW smem chain, keeping ~4 loads in
// flight per warp through the chain. surface = max(0, max_f - mean).
// ---------------------------------------------------------------------------
#define RMW1(f, k) do {                               \
    float2 _v = ap[(k) * 32];                         \
    _v.x += (f); _v.y = fmaxf(_v.y, (f));             \
    ap[(k) * 32] = _v;                                \
} while (0)

#define RMW8(a0, q0, a1, q1) do {                     \
    RMW1((a0).x, (q0) & 255);                         \
    RMW1((a0).y, ((q0) >> 8) & 255);                  \
    RMW1((a0).z, ((q0) >> 16) & 255);                 \
    RMW1((a0).w, (q0) >> 24);                         \
    RMW1((a1).x, (q1) & 255);                         \
    RMW1((a1).y, ((q1) >> 8) & 255);                  \
    RMW1((a1).z, ((q1) >> 16) & 255);                 \
    RMW1((a1).w, (q1) >> 24);                         \
} while (0)

__global__ __launch_bounds__(128) void feat_kernel(
    const float* __restrict__ features, float* __restrict__ out, int N, int C)
{
    const int w    = threadIdx.x >> 5;
    const int lane = threadIdx.x & 31;
    const int cpb  = C >> 2;                      // channel groups of 4
    const int b = blockIdx.x / cpb;
    const int c = ((blockIdx.x % cpb) << 2) + w;

    __shared__ float2 acc[4][NPARTS][32];         // 24 KB
    float2* ap = &acc[w][0][lane];                // stride between k's = 32 float2

    #pragma unroll
    for (int k = 0; k < NPARTS; ++k)
        ap[k * 32] = make_float2(0.f, -CUDART_INF_F);
    __syncwarp();

    const float4* __restrict__ fr =
        (const float4*)(features + ((size_t)b * C + c) * N);
    const unsigned* __restrict__ lr = g_labels8 + (((size_t)b * N) >> 2);

    const int iters = N >> 8;                     // 256 points per warp-iter

    // prologue: loads for iter 0
    float4   a0 = fr[lane],  a1 = fr[32 + lane];
    unsigned q0 = lr[lane],  q1 = lr[32 + lane];

    for (int i = 0; i < iters - 1; ++i) {
        const int nb = (i + 1) << 6;
        // prefetch iter i+1 BEFORE the dependent RMW chain of iter i
        const float4   n0 = fr[nb + lane],  n1 = fr[nb + 32 + lane];
        const unsigned r0 = lr[nb + lane],  r1 = lr[nb + 32 + lane];

        RMW8(a0, q0, a1, q1);

        a0 = n0; a1 = n1; q0 = r0; q1 = r1;
    }
    RMW8(a0, q0, a1, q1);                         // epilogue iter
    __syncwarp();

    const int outd = 3 + 2 * C;
    for (int k = 0; k < NPARTS; ++k) {
        float2 v = ap[k * 32];
        #pragma unroll
        for (int off = 16; off; off >>= 1) {
            v.x += __shfl_xor_sync(0xFFFFFFFFu, v.x, off);
            v.y = fmaxf(v.y, __shfl_xor_sync(0xFFFFFFFFu, v.y, off));
        }
        if (lane == 0) {
            const float denom = fmaxf(g_counts[b * NPARTS + k], 1.f);
            const float mean = v.x / denom;
            float* o = out + ((size_t)b * NPARTS + k) * outd + 3;
            o[c]     = mean;
            o[C + c] = fmaxf(v.y - mean, 0.f);    // empty seg: -inf - 0 -> 0
        }
    }
}

extern "C" void kernel_launch(void* const* d_in, const int* in_sizes, int n_in,
                              void* d_out, int out_size)
{
    const float* xyz      = (const float*)d_in[0];
    const float* features = (const float*)d_in[1];
    const int*   labels   = (const int*)d_in[2];
    float* out = (float*)d_out;

    const long long BN = in_sizes[2];                  // B*N
    const int C = (int)((long long)in_sizes[1] / BN);  // 128
    const int outd = 3 + 2 * C;                        // 259
    const int B = out_size / (NPARTS * outd);          // 64
    const int N = (int)(BN / B);                       // 16384

    xyz_partial_kernel<<<B * SLOTS, 128>>>(xyz, labels, N);
    xyz_merge_kernel<<<(B * NPARTS + 127) / 128, 128>>>(out, C, B);
    feat_kernel<<<B * (C / 4), 128>>>(features, out, N, C);
}

// round 7
// speedup vs baseline: 1.2608x; 1.0736x over previous
#include <cuda_runtime.h>
#include <cuda_bf16.h>
#include <math_constants.h>

#define NPARTS 24
#define MAXB   64
#define MAXN   16384
#define MAXC   128
#define SLOTS  8     // xyz partial blocks per batch
#define NH     2     // n-halves per channel-pair in feat kernel

// __device__ scratch (allocation-free per harness rules)
__device__ unsigned int g_labels8[(MAXB * MAXN) / 4];       // u8-packed labels, 1 MB
__device__ float4       g_part[MAXB * SLOTS * NPARTS];      // partial xyz {x,y,z,count}
__device__ float2       g_feat[MAXB * (MAXC/2) * NH * NPARTS * 2]; // per-warp {sum,max} partials

// ---------------------------------------------------------------------------
// Kernel 1: per-chunk xyz partial sums + counts, and pack labels to u8.
// Grid = B*SLOTS blocks, 128 threads (4 warps). Lane-private smem float4
// accumulators, no atomics. Tail reduction distributed over all 4 warps
// (6 parts each) instead of warp 0 doing all 24.
// ---------------------------------------------------------------------------
__global__ __launch_bounds__(128) void xyz_partial_kernel(
    const float* __restrict__ xyz, const int* __restrict__ labels, int N)
{
    const int b    = blockIdx.x / SLOTS;
    const int s    = blockIdx.x % SLOTS;
    const int w    = threadIdx.x >> 5;
    const int lane = threadIdx.x & 31;

    __shared__ float4 acc[4][NPARTS][32];
    #pragma unroll
    for (int k = 0; k < NPARTS; ++k)
        acc[w][k][lane] = make_float4(0.f, 0.f, 0.f, 0.f);
    __syncthreads();

    const int chunk  = N / SLOTS;                 // points per block
    const int groups = chunk >> 2;                // 4-point groups per block
    const int g0     = (b * N + s * chunk) >> 2;  // global 4-point group base

    const int4*   __restrict__ l4 = (const int4*)labels;
    const float4* __restrict__ x4 = (const float4*)xyz;

    for (int g = threadIdx.x; g < groups; g += 128) {
        const int gg = g0 + g;
        const int4 li = l4[gg];
        g_labels8[gg] = (unsigned)li.x | ((unsigned)li.y << 8) |
                        ((unsigned)li.z << 16) | ((unsigned)li.w << 24);
        const float4 p0 = x4[3 * gg + 0];
        const float4 p1 = x4[3 * gg + 1];
        const float4 p2 = x4[3 * gg + 2];
        float4 v;
        v = acc[w][li.x][lane]; v.x += p0.x; v.y += p0.y; v.z += p0.z; v.w += 1.f; acc[w][li.x][lane] = v;
        v = acc[w][li.y][lane]; v.x += p0.w; v.y += p1.x; v.z += p1.y; v.w += 1.f; acc[w][li.y][lane] = v;
        v = acc[w][li.z][lane]; v.x += p1.z; v.y += p1.w; v.z += p2.x; v.w += 1.f; acc[w][li.z][lane] = v;
        v = acc[w][li.w][lane]; v.x += p2.y; v.y += p2.z; v.z += p2.w; v.w += 1.f; acc[w][li.w][lane] = v;
    }
    __syncthreads();

    // distributed tail: warp w reduces parts [6w, 6w+6)
    #pragma unroll
    for (int j = 0; j < NPARTS / 4; ++j) {
        const int k = w * (NPARTS / 4) + j;
        const float4 a0 = acc[0][k][lane], a1 = acc[1][k][lane];
        const float4 a2 = acc[2][k][lane], a3 = acc[3][k][lane];
        float4 v = make_float4(a0.x + a1.x + a2.x + a3.x,
                               a0.y + a1.y + a2.y + a3.y,
                               a0.z + a1.z + a2.z + a3.z,
                               a0.w + a1.w + a2.w + a3.w);
        #pragma unroll
        for (int off = 16; off; off >>= 1) {
            v.x += __shfl_xor_sync(0xFFFFFFFFu, v.x, off);
            v.y += __shfl_xor_sync(0xFFFFFFFFu, v.y, off);
            v.z += __shfl_xor_sync(0xFFFFFFFFu, v.z, off);
            v.w += __shfl_xor_sync(0xFFFFFFFFu, v.w, off);
        }
        if (lane == 0)
            g_part[blockIdx.x * NPARTS + k] = v;
    }
}

// ---------------------------------------------------------------------------
// Kernel 2: feat pair-scheme. 2-warp blocks (12 KB smem). Each warp covers
// 2 channels over one n-half: even lanes = chan c0, odd lanes = chan c0+1;
// 16 lane-pairs own the point columns. Accumulator cell = float4
// {sumA,maxA,sumB,maxB}; each lane RMWs its float2 half (conflict-free).
// Depth-2 software pipeline keeps 2x512B feature loads in flight per warp.
// ---------------------------------------------------------------------------
#define RMW1(f, k) do {                               \
    float2 _v = ap[(k) * 32];                         \
    _v.x += (f); _v.y = fmaxf(_v.y, (f));             \
    ap[(k) * 32] = _v;                                \
} while (0)

#define RMW4(f, q) do {                               \
    RMW1((f).x, (q) & 255);                           \
    RMW1((f).y, ((q) >> 8) & 255);                    \
    RMW1((f).z, ((q) >> 16) & 255);                   \
    RMW1((f).w, (q) >> 24);                           \
} while (0)

__global__ __launch_bounds__(64) void feat_kernel(
    const float* __restrict__ features, int N, int C)
{
    const int w    = threadIdx.x >> 5;
    const int lane = threadIdx.x & 31;
    const int pair = lane >> 1;
    const int odd  = lane & 1;

    const int tasks_per_b = (C / 2) * NH;         // 128
    const int gwid = blockIdx.x * 2 + w;
    const int b  = gwid / tasks_per_b;
    const int r  = gwid % tasks_per_b;
    const int cp = r >> 1;                        // channel pair
    const int h  = r & 1;                         // n-half

    __shared__ float4 acc[2][NPARTS][16];         // 12 KB
    float2* ap = (float2*)((char*)(&acc[w][0][0]) + pair * 16 + odd * 8);
    // cell for part k at ap[k*32] (k stride = 16 float4 = 32 float2)

    #pragma unroll
    for (int k = 0; k < NPARTS; ++k)
        ap[k * 32] = make_float2(0.f, -CUDART_INF_F);
    __syncwarp();

    const int c = cp * 2 + odd;
    const float4* __restrict__ fr =
        (const float4*)features + ((size_t)(b * C + c) * (N >> 2));
    const unsigned* __restrict__ lr = g_labels8 + (((size_t)b * N) >> 2);

    const int half4 = N >> 3;                     // float4 words per half (2048)
    const int base  = h * half4;
    const int iters = half4 >> 4;                 // 16 words per warp-iter (128)

    // depth-2 pipeline prologue
    float4   f0 = __ldcs(&fr[base + pair]);
    unsigned q0 = lr[base + pair];
    float4   f1 = __ldcs(&fr[base + 16 + pair]);
    unsigned q1 = lr[base + 16 + pair];

    for (int i = 0; i < iters - 2; ++i) {
        const int nb = base + (i + 2) * 16 + pair;
        const float4   f2 = __ldcs(&fr[nb]);
        const unsigned q2 = lr[nb];
        RMW4(f0, q0);
        f0 = f1; q0 = q1; f1 = f2; q1 = q2;
    }
    RMW4(f0, q0);
    RMW4(f1, q1);
    __syncwarp();

    // reduce over the 16 pairs (shuffles among same-parity lanes)
    for (int k = 0; k < NPARTS; ++k) {
        float2 v = ap[k * 32];
        #pragma unroll
        for (int off = 2; off < 32; off <<= 1) {
            v.x += __shfl_xor_sync(0xFFFFFFFFu, v.x, off);
            v.y = fmaxf(v.y, __shfl_xor_sync(0xFFFFFFFFu, v.y, off));
        }
        if (lane < 2)   // lane0 = chan A total, lane1 = chan B total
            g_feat[gwid * (2 * NPARTS) + 2 * k + odd] = v;
    }
}

// ---------------------------------------------------------------------------
// Kernel 3: merge. One thread per (b, channel-pair, k): combines the NH
// feat partials, recomputes the count from xyz partials (L2-broadcast,
// tiny), writes mean/surface; cp==0 threads also write mean_xyz.
// ---------------------------------------------------------------------------
__global__ void merge_kernel(float* __restrict__ out, int C, int B)
{
    const int total = B * (C / 2) * NPARTS;
    const int i = blockIdx.x * blockDim.x + threadIdx.x;
    if (i >= total) return;
    const int k  = i % NPARTS;
    const int t  = i / NPARTS;
    const int cp = t % (C / 2);
    const int b  = t / (C / 2);

    float sx = 0.f, sy = 0.f, sz = 0.f, cnt = 0.f;
    #pragma unroll
    for (int s = 0; s < SLOTS; ++s) {
        const float4 v = g_part[(b * SLOTS + s) * NPARTS + k];
        sx += v.x; sy += v.y; sz += v.z; cnt += v.w;
    }
    const float denom = fmaxf(cnt, 1.f);

    const int outd = 3 + 2 * C;
    float* o = out + ((size_t)(b * NPARTS + k)) * outd;
    if (cp == 0) {
        o[0] = sx / denom;
        o[1] = sy / denom;
        o[2] = sz / denom;
    }

    const int g0 = (b * (C / 2) + cp) * NH;       // gwid of h=0
    const float2 a0 = g_feat[(g0 + 0) * (2 * NPARTS) + 2 * k + 0];
    const float2 a1 = g_feat[(g0 + 1) * (2 * NPARTS) + 2 * k + 0];
    const float2 b0 = g_feat[(g0 + 0) * (2 * NPARTS) + 2 * k + 1];
    const float2 b1 = g_feat[(g0 + 1) * (2 * NPARTS) + 2 * k + 1];

    const float meanA = (a0.x + a1.x) / denom;
    const float meanB = (b0.x + b1.x) / denom;
    const float maxA  = fmaxf(a0.y, a1.y);
    const float maxB  = fmaxf(b0.y, b1.y);

    const int c0 = cp * 2;
    o[3 + c0]         = meanA;
    o[3 + c0 + 1]     = meanB;
    o[3 + C + c0]     = fmaxf(maxA - meanA, 0.f);  // empty seg: -inf -> 0
    o[3 + C + c0 + 1] = fmaxf(maxB - meanB, 0.f);
}

extern "C" void kernel_launch(void* const* d_in, const int* in_sizes, int n_in,
                              void* d_out, int out_size)
{
    const float* xyz      = (const float*)d_in[0];
    const float* features = (const float*)d_in[1];
    const int*   labels   = (const int*)d_in[2];
    float* out = (float*)d_out;

    const long long BN = in_sizes[2];                  // B*N
    const int C = (int)((long long)in_sizes[1] / BN);  // 128
    const int outd = 3 + 2 * C;                        // 259
    const int B = out_size / (NPARTS * outd);          // 64
    const int N = (int)(BN / B);                       // 16384

    xyz_partial_kernel<<<B * SLOTS, 128>>>(xyz, labels, N);
    feat_kernel<<<B * (C / 2) * NH / 2, 64>>>(features, N, C);
    merge_kernel<<<(B * (C / 2) * NPARTS + 255) / 256, 256>>>(out, C, B);
}